// round 11
// baseline (speedup 1.0000x reference)
#include <cuda_runtime.h>
#include <cuda_bf16.h>
#include <cstdint>
#include <math.h>

// Problem constants
#define BB   2
#define LL   2048
#define DD   1024
#define DIM  2048      // d_inner
#define DS   16        // d_state
#define DTRK 64        // dt_rank
#define NXD  96        // DTR + 2*DS
#define BL   (BB*LL)   // 4096 rows
#define NC   16        // scan chunks
#define CS   (LL/NC)   // 128 steps per chunk
#define KSPL 8         // x_proj split-K factor

// ---------------- scratch ----------------------------------------------------
__device__ __align__(256) float g_xz[(size_t)BL * 2 * DIM];
__device__ __align__(256) float g_xdbl[(size_t)BL * NXD];
__device__ __align__(256) float g_xpart[(size_t)KSPL * BL * NXD];
__device__ __align__(256) float g_dtraw[(size_t)BL * DIM];   // dt linear -> dtv (in-place)
__device__ __align__(256) float g_hend[(size_t)BB * NC * DS * DIM];
__device__ __align__(256) float g_P[(size_t)BB * NC * DS * DIM];

__device__ __align__(256) __nv_bfloat16 g_h_hi[(size_t)BL * DD],    g_h_lo[(size_t)BL * DD];
__device__ __align__(256) __nv_bfloat16 g_wi_hi[(size_t)2*DIM*DD],  g_wi_lo[(size_t)2*DIM*DD];
__device__ __align__(256) __nv_bfloat16 g_xc_hi[(size_t)BL * DIM],  g_xc_lo[(size_t)BL * DIM];
__device__ __align__(256) __nv_bfloat16 g_xp_hi[(size_t)NXD * DIM], g_xp_lo[(size_t)NXD * DIM];
__device__ __align__(256) __nv_bfloat16 g_dta_hi[(size_t)BL * DTRK],g_dta_lo[(size_t)BL * DTRK];
__device__ __align__(256) __nv_bfloat16 g_dtw_hi[(size_t)DIM*DTRK], g_dtw_lo[(size_t)DIM*DTRK];
__device__ __align__(256) __nv_bfloat16 g_y_hi[(size_t)BL * DIM],   g_y_lo[(size_t)BL * DIM];
__device__ __align__(256) __nv_bfloat16 g_ow_hi[(size_t)DD * DIM],  g_ow_lo[(size_t)DD * DIM];

// ---------------- helpers ----------------------------------------------------
__device__ __forceinline__ uint32_t smem_u32(const void* p) {
    uint32_t a;
    asm("{ .reg .u64 t; cvta.to.shared.u64 t, %1; cvt.u32.u64 %0, t; }"
        : "=r"(a) : "l"(p));
    return a;
}
__device__ __forceinline__ void split_bf16(float v, __nv_bfloat16& hi, __nv_bfloat16& lo) {
    hi = __float2bfloat16(v);
    lo = __float2bfloat16(v - __bfloat162float(hi));
}
__device__ __forceinline__ float softplus_f(float x) {
    return (x > 20.f) ? x : log1pf(__expf(x));
}
// powers E^1..E^16 via depth-4 tree
__device__ __forceinline__ void pow_tree(float E, float pw[DS]) {
    float E2 = E * E, E4 = E2 * E2, E8 = E4 * E4;
    pw[0] = E;        pw[1] = E2;       pw[2] = E2 * E;   pw[3] = E4;
    pw[4] = E4 * E;   pw[5] = E4 * E2;  pw[6] = E4 * pw[2]; pw[7] = E8;
    pw[8] = E8 * E;   pw[9] = E8 * E2;  pw[10] = E8 * pw[2]; pw[11] = E8 * E4;
    pw[12] = E8 * pw[4]; pw[13] = E8 * pw[5]; pw[14] = E8 * pw[6]; pw[15] = E8 * E8;
}

__device__ __forceinline__ void ldm_x4(uint32_t addr, uint32_t r[4]) {
    asm volatile("ldmatrix.sync.aligned.m8n8.x4.shared.b16 {%0,%1,%2,%3}, [%4];"
        : "=r"(r[0]), "=r"(r[1]), "=r"(r[2]), "=r"(r[3]) : "r"(addr));
}
__device__ __forceinline__ void mma_bf16(float d[4], const uint32_t a[4],
                                         uint32_t b0, uint32_t b1) {
    asm volatile(
        "mma.sync.aligned.m16n8k16.row.col.f32.bf16.bf16.f32 "
        "{%0,%1,%2,%3}, {%4,%5,%6,%7}, {%8,%9}, {%0,%1,%2,%3};"
        : "+f"(d[0]), "+f"(d[1]), "+f"(d[2]), "+f"(d[3])
        : "r"(a[0]), "r"(a[1]), "r"(a[2]), "r"(a[3]), "r"(b0), "r"(b1));
}
__device__ __forceinline__ void cp16(uint32_t dst, const void* src, int srcsize) {
    asm volatile("cp.async.cg.shared.global [%0], [%1], 16, %2;"
                 :: "r"(dst), "l"(src), "r"(srcsize));
}
__device__ __forceinline__ void cp_commit() {
    asm volatile("cp.async.commit_group;");
}
__device__ __forceinline__ void cp_wait2() {
    asm volatile("cp.async.wait_group 2;");
}

// ======== tc_gemm2: 128x256 CTA tile, 64x64 warp tiles (2m x 4n) =============
// For GEMMs with M%128==0, N%256==0, K%32==0. 1 CTA/SM, 3-stage pipeline.
// Smem stage: Ahi 8K | Alo 8K | Bhi 16K | Blo 16K = 48KB.
#define T2_AHI 0
#define T2_ALO 8192
#define T2_BHI 16384
#define T2_BLO 32768
#define STAGE2 49152
#define GSMEM2 (3 * STAGE2)        // 147456 B

__global__ __launch_bounds__(256, 1) void tc_gemm2(
    const __nv_bfloat16* __restrict__ Ahi, const __nv_bfloat16* __restrict__ Alo,
    const __nv_bfloat16* __restrict__ Bhi, const __nv_bfloat16* __restrict__ Blo,
    float* __restrict__ C, int ldc, int K)
{
    extern __shared__ char smem[];
    const uint32_t sbase = smem_u32(smem);
    const int tid  = threadIdx.x;
    const int wid  = tid >> 5;
    const int lane = tid & 31;
    const int warp_m = wid & 1;          // 0..1 -> 64-row slice
    const int warp_n = wid >> 1;         // 0..3 -> 64-col slice
    const int m0 = blockIdx.y * 128;
    const int n0 = blockIdx.x * 256;

    const __nv_bfloat16* srcA[2] = { Ahi + (size_t)m0 * K, Alo + (size_t)m0 * K };
    const __nv_bfloat16* srcB[2] = { Bhi + (size_t)n0 * K, Blo + (size_t)n0 * K };

    float acc[4][8][4];
    #pragma unroll
    for (int a = 0; a < 4; a++)
        #pragma unroll
        for (int b = 0; b < 8; b++)
            #pragma unroll
            for (int c = 0; c < 4; c++) acc[a][b][c] = 0.f;

    const int nch = K / 32;

    auto load_chunk = [&](int stage, int k0) {
        const uint32_t base = sbase + stage * STAGE2;
        // A: 2 tiles x (128 rows x 4 c) = 1024 cp16; 4 per thread
        #pragma unroll
        for (int i = 0; i < 4; i++) {
            const int tile = i >> 1;
            const int idx  = ((i & 1) << 8) + tid;   // 0..511
            const int row  = idx >> 2;
            const int c    = idx & 3;
            const int csw  = c ^ ((row >> 1) & 3);
            const uint32_t dst = base + (tile ? T2_ALO : T2_AHI) + row * 64 + csw * 16;
            cp16(dst, srcA[tile] + (size_t)row * K + k0 + c * 8, 16);
        }
        // B: 2 tiles x (256 rows x 4 c) = 2048 cp16; 8 per thread
        #pragma unroll
        for (int i = 0; i < 8; i++) {
            const int tile = i >> 2;
            const int idx  = ((i & 3) << 8) + tid;   // 0..1023
            const int row  = idx >> 2;
            const int c    = idx & 3;
            const int csw  = c ^ ((row >> 1) & 3);
            const uint32_t dst = base + (tile ? T2_BLO : T2_BHI) + row * 64 + csw * 16;
            cp16(dst, srcB[tile] + (size_t)row * K + k0 + c * 8, 16);
        }
    };

    load_chunk(0, 0);
    cp_commit();
    if (1 < nch) load_chunk(1, 32);
    cp_commit();

    for (int ch = 0; ch < nch; ch++) {
        if (ch + 2 < nch) load_chunk((ch + 2) % 3, (ch + 2) * 32);
        cp_commit();
        cp_wait2();
        __syncthreads();

        const uint32_t st = sbase + (ch % 3) * STAGE2;

        #pragma unroll
        for (int k16 = 0; k16 < 2; k16++) {
            const int ci = k16 * 2 + (lane >> 4);
            uint32_t ah[4][4], al[4][4];
            #pragma unroll
            for (int mf = 0; mf < 4; mf++) {
                const int row = warp_m * 64 + mf * 16 + (lane & 15);
                const uint32_t off = row * 64 + ((ci ^ ((row >> 1) & 3)) * 16);
                ldm_x4(st + T2_AHI + off, ah[mf]);
                ldm_x4(st + T2_ALO + off, al[mf]);
            }
            #pragma unroll
            for (int nb = 0; nb < 4; nb++) {
                uint32_t bh[4], bl[4];
                const int rowb = warp_n * 64 + nb * 16 + (lane & 15);
                const uint32_t offb = rowb * 64 + ((ci ^ ((rowb >> 1) & 3)) * 16);
                ldm_x4(st + T2_BHI + offb, bh);
                ldm_x4(st + T2_BLO + offb, bl);
                #pragma unroll
                for (int mf = 0; mf < 4; mf++) {
                    mma_bf16(acc[mf][nb*2],   ah[mf], bh[0], bh[2]);
                    mma_bf16(acc[mf][nb*2+1], ah[mf], bh[1], bh[3]);
                }
                #pragma unroll
                for (int mf = 0; mf < 4; mf++) {
                    mma_bf16(acc[mf][nb*2],   ah[mf], bl[0], bl[2]);
                    mma_bf16(acc[mf][nb*2+1], ah[mf], bl[1], bl[3]);
                }
                #pragma unroll
                for (int mf = 0; mf < 4; mf++) {
                    mma_bf16(acc[mf][nb*2],   al[mf], bh[0], bh[2]);
                    mma_bf16(acc[mf][nb*2+1], al[mf], bh[1], bh[3]);
                }
            }
        }
        __syncthreads();
    }

    #pragma unroll
    for (int mf = 0; mf < 4; mf++) {
        #pragma unroll
        for (int nf = 0; nf < 8; nf++) {
            const int r0  = m0 + warp_m * 64 + mf * 16 + (lane >> 2);
            const int col = n0 + warp_n * 64 + nf * 8 + (lane & 3) * 2;
            float2 v0 = make_float2(acc[mf][nf][0], acc[mf][nf][1]);
            float2 v1 = make_float2(acc[mf][nf][2], acc[mf][nf][3]);
            *reinterpret_cast<float2*>(C + (size_t)r0 * ldc + col) = v0;
            *reinterpret_cast<float2*>(C + (size_t)(r0 + 8) * ldc + col) = v1;
        }
    }
}

// ======== tc_gemm: 128x128 tile, N-guarded, split-K (x_proj only) ============
#define TILEB 8192
#define STAGE3 (4 * TILEB)
#define GSMEM (3 * STAGE3)

__global__ __launch_bounds__(256, 2) void tc_gemm(
    const __nv_bfloat16* __restrict__ Ahi, const __nv_bfloat16* __restrict__ Alo,
    const __nv_bfloat16* __restrict__ Bhi, const __nv_bfloat16* __restrict__ Blo,
    float* __restrict__ C, int ldc, int N, int ldK, int Ksub, long cstride)
{
    extern __shared__ char smem[];
    const uint32_t sbase = smem_u32(smem);
    const int tid  = threadIdx.x;
    const int wid  = tid >> 5;
    const int lane = tid & 31;
    const int warp_m = wid & 3;
    const int warp_n = wid >> 2;
    const int m0 = blockIdx.y * 128;
    const int n0 = blockIdx.x * 128;
    const int kbase = blockIdx.z * Ksub;
    C += (long)blockIdx.z * cstride;

    const __nv_bfloat16* srcA[2] = { Ahi + (size_t)m0 * ldK + kbase,
                                     Alo + (size_t)m0 * ldK + kbase };
    const __nv_bfloat16* srcB[2] = { Bhi + (size_t)n0 * ldK + kbase,
                                     Blo + (size_t)n0 * ldK + kbase };

    float acc[2][8][4];
    #pragma unroll
    for (int a = 0; a < 2; a++)
        #pragma unroll
        for (int b = 0; b < 8; b++)
            #pragma unroll
            for (int c = 0; c < 4; c++) acc[a][b][c] = 0.f;

    const int nch = Ksub / 32;

    auto load_chunk = [&](int stage, int k0) {
        const uint32_t base = sbase + stage * STAGE3;
        #pragma unroll
        for (int i = 0; i < 8; i++) {
            const int tile = i >> 1;
            const int rem  = ((i & 1) << 8) + tid;
            const int row  = rem >> 2;
            const int c    = rem & 3;
            const int csw  = c ^ ((row >> 1) & 3);
            const uint32_t dst = base + tile * TILEB + row * 64 + csw * 16;
            const __nv_bfloat16* g;
            int sz = 16;
            if (tile < 2) {
                g = srcA[tile] + (size_t)row * ldK + k0 + c * 8;
            } else {
                g = srcB[tile - 2] + (size_t)row * ldK + k0 + c * 8;
                if (n0 + row >= N) sz = 0;
            }
            cp16(dst, g, sz);
        }
    };

    load_chunk(0, 0);
    cp_commit();
    if (1 < nch) load_chunk(1, 32);
    cp_commit();

    for (int ch = 0; ch < nch; ch++) {
        if (ch + 2 < nch) load_chunk((ch + 2) % 3, (ch + 2) * 32);
        cp_commit();
        cp_wait2();
        __syncthreads();

        const uint32_t st = sbase + (ch % 3) * STAGE3;
        const uint32_t aHiB = st;
        const uint32_t aLoB = st + TILEB;
        const uint32_t bHiB = st + 2 * TILEB;
        const uint32_t bLoB = st + 3 * TILEB;

        #pragma unroll
        for (int k16 = 0; k16 < 2; k16++) {
            uint32_t ah[2][4], al[2][4], bh[4][4], bl[4][4];
            const int ci = k16 * 2 + (lane >> 4);
            #pragma unroll
            for (int mf = 0; mf < 2; mf++) {
                const int row = warp_m * 32 + mf * 16 + (lane & 15);
                const uint32_t off = row * 64 + ((ci ^ ((row >> 1) & 3)) * 16);
                ldm_x4(aHiB + off, ah[mf]);
                ldm_x4(aLoB + off, al[mf]);
            }
            #pragma unroll
            for (int nb = 0; nb < 4; nb++) {
                const int rowb = warp_n * 64 + nb * 16 + (lane & 15);
                const uint32_t offb = rowb * 64 + ((ci ^ ((rowb >> 1) & 3)) * 16);
                ldm_x4(bHiB + offb, bh[nb]);
                ldm_x4(bLoB + offb, bl[nb]);
            }
            #pragma unroll
            for (int mf = 0; mf < 2; mf++)
                #pragma unroll
                for (int nb = 0; nb < 4; nb++) {
                    mma_bf16(acc[mf][nb*2],   ah[mf], bh[nb][0], bh[nb][2]);
                    mma_bf16(acc[mf][nb*2+1], ah[mf], bh[nb][1], bh[nb][3]);
                }
            #pragma unroll
            for (int mf = 0; mf < 2; mf++)
                #pragma unroll
                for (int nb = 0; nb < 4; nb++) {
                    mma_bf16(acc[mf][nb*2],   ah[mf], bl[nb][0], bl[nb][2]);
                    mma_bf16(acc[mf][nb*2+1], ah[mf], bl[nb][1], bl[nb][3]);
                }
            #pragma unroll
            for (int mf = 0; mf < 2; mf++)
                #pragma unroll
                for (int nb = 0; nb < 4; nb++) {
                    mma_bf16(acc[mf][nb*2],   al[mf], bh[nb][0], bh[nb][2]);
                    mma_bf16(acc[mf][nb*2+1], al[mf], bh[nb][1], bh[nb][3]);
                }
        }
        __syncthreads();
    }

    #pragma unroll
    for (int mf = 0; mf < 2; mf++) {
        #pragma unroll
        for (int nf = 0; nf < 8; nf++) {
            const int r0  = m0 + warp_m * 32 + mf * 16 + (lane >> 2);
            const int col = n0 + warp_n * 64 + nf * 8 + (lane & 3) * 2;
            if (col < N) {
                float2 v0 = make_float2(acc[mf][nf][0], acc[mf][nf][1]);
                float2 v1 = make_float2(acc[mf][nf][2], acc[mf][nf][3]);
                *reinterpret_cast<float2*>(C + (size_t)r0 * ldc + col) = v0;
                *reinterpret_cast<float2*>(C + (size_t)(r0 + 8) * ldc + col) = v1;
            }
        }
    }
}

// ---------------- split-K reduce for x_proj + fused dt-slice cvt -------------
__global__ __launch_bounds__(256) void xpart_reduce_kernel(
    const float* __restrict__ part, float* __restrict__ xdbl,
    __nv_bfloat16* __restrict__ dta_hi, __nv_bfloat16* __restrict__ dta_lo)
{
    int i = blockIdx.x * blockDim.x + threadIdx.x;
    if (i >= BL * NXD) return;
    float s = 0.f;
    #pragma unroll
    for (int z = 0; z < KSPL; z++) s += part[(size_t)z * BL * NXD + i];
    xdbl[i] = s;
    int col = i % NXD;
    if (col < DTRK) {
        int row = i / NXD;
        __nv_bfloat16 h, l; split_bf16(s, h, l);
        dta_hi[(size_t)row * DTRK + col] = h;
        dta_lo[(size_t)row * DTRK + col] = l;
    }
}

// ---------------- weight conversions ----------------------------------------
__global__ __launch_bounds__(256) void cvt_flat_kernel(
    const float* __restrict__ src, long total,
    __nv_bfloat16* __restrict__ hi, __nv_bfloat16* __restrict__ lo)
{
    long i = (long)blockIdx.x * blockDim.x + threadIdx.x;
    if (i >= total) return;
    __nv_bfloat16 h, l; split_bf16(src[i], h, l);
    hi[i] = h; lo[i] = l;
}

#define C1 ((long)NXD * DIM)
#define C2 (C1 + (long)DIM * DTRK)
#define C3 (C2 + (long)DD * DIM)
__global__ __launch_bounds__(256) void cvt_rest_kernel(
    const float* __restrict__ s0, const float* __restrict__ s1,
    const float* __restrict__ s2,
    __nv_bfloat16* __restrict__ h0, __nv_bfloat16* __restrict__ l0,
    __nv_bfloat16* __restrict__ h1, __nv_bfloat16* __restrict__ l1,
    __nv_bfloat16* __restrict__ h2, __nv_bfloat16* __restrict__ l2)
{
    long i = (long)blockIdx.x * blockDim.x + threadIdx.x;
    if (i >= C3) return;
    const float* s; __nv_bfloat16 *ph, *pl; long j;
    if (i < C1)      { s = s0; ph = h0; pl = l0; j = i; }
    else if (i < C2) { s = s1; ph = h1; pl = l1; j = i - C1; }
    else             { s = s2; ph = h2; pl = l2; j = i - C2; }
    __nv_bfloat16 h, l; split_bf16(s[j], h, l);
    ph[j] = h; pl[j] = l;
}

// ---------------- fused add + LayerNorm (emits residual + h hi/lo) ----------
__global__ __launch_bounds__(256) void addnorm_kernel(
    const float* __restrict__ x, const float* __restrict__ res,
    const float* __restrict__ w, const float* __restrict__ b,
    float* __restrict__ res_out,
    __nv_bfloat16* __restrict__ h_hi, __nv_bfloat16* __restrict__ h_lo)
{
    const int row = blockIdx.x;
    const int tid = threadIdx.x;
    const float4* xv = reinterpret_cast<const float4*>(x + (size_t)row * DD);
    const float4* rv = reinterpret_cast<const float4*>(res + (size_t)row * DD);
    float4 a = xv[tid], r = rv[tid];
    float4 v = make_float4(a.x + r.x, a.y + r.y, a.z + r.z, a.w + r.w);
    reinterpret_cast<float4*>(res_out + (size_t)row * DD)[tid] = v;

    float s  = v.x + v.y + v.z + v.w;
    float ss = v.x*v.x + v.y*v.y + v.z*v.z + v.w*v.w;
    __shared__ float red[16];
    #pragma unroll
    for (int o = 16; o > 0; o >>= 1) {
        s  += __shfl_xor_sync(0xFFFFFFFFu, s,  o);
        ss += __shfl_xor_sync(0xFFFFFFFFu, ss, o);
    }
    int wid = tid >> 5, lane = tid & 31;
    if (lane == 0) { red[wid] = s; red[8 + wid] = ss; }
    __syncthreads();
    if (tid == 0) {
        float ts = 0.f, tss = 0.f;
        #pragma unroll
        for (int i = 0; i < 8; i++) { ts += red[i]; tss += red[8 + i]; }
        float mean = ts * (1.f / DD);
        float var  = tss * (1.f / DD) - mean * mean;
        red[0] = mean; red[1] = rsqrtf(var + 1e-5f);
    }
    __syncthreads();
    float mean = red[0], rstd = red[1];
    float4 wv = reinterpret_cast<const float4*>(w)[tid];
    float4 bv = reinterpret_cast<const float4*>(b)[tid];
    float hv[4];
    hv[0] = (v.x - mean) * rstd * wv.x + bv.x;
    hv[1] = (v.y - mean) * rstd * wv.y + bv.y;
    hv[2] = (v.z - mean) * rstd * wv.z + bv.z;
    hv[3] = (v.w - mean) * rstd * wv.w + bv.w;
    __nv_bfloat16 hh[4], ll[4];
    #pragma unroll
    for (int i = 0; i < 4; i++) split_bf16(hv[i], hh[i], ll[i]);
    size_t o = (size_t)row * DD + tid * 4;
    *reinterpret_cast<uint2*>(h_hi + o) = *reinterpret_cast<uint2*>(hh);
    *reinterpret_cast<uint2*>(h_lo + o) = *reinterpret_cast<uint2*>(ll);
}

// ---------------- causal depthwise conv (DC=4) + SiLU (hi/lo only) -----------
__global__ __launch_bounds__(256) void conv_silu_kernel(
    const float* __restrict__ xz, const float* __restrict__ cw,
    const float* __restrict__ cb,
    __nv_bfloat16* __restrict__ xc_hi, __nv_bfloat16* __restrict__ xc_lo)
{
    int idx = blockIdx.x * blockDim.x + threadIdx.x;
    if (idx >= BB * LL * DIM) return;
    int d = idx % DIM;
    int t = (idx / DIM) % LL;
    int b = idx / (DIM * LL);
    float w0 = cw[d * 4 + 0], w1 = cw[d * 4 + 1];
    float w2 = cw[d * 4 + 2], w3 = cw[d * 4 + 3];
    size_t base = ((size_t)(b * LL + t)) * (2 * DIM) + d;
    float acc = cb[d];
    if (t >= 3) acc = fmaf(xz[base - 3 * (size_t)(2 * DIM)], w0, acc);
    if (t >= 2) acc = fmaf(xz[base - 2 * (size_t)(2 * DIM)], w1, acc);
    if (t >= 1) acc = fmaf(xz[base - 1 * (size_t)(2 * DIM)], w2, acc);
    acc = fmaf(xz[base], w3, acc);
    float sg = 1.f / (1.f + __expf(-acc));
    float v = acc * sg;
    __nv_bfloat16 h, l; split_bf16(v, h, l);
    xc_hi[idx] = h; xc_lo[idx] = l;
}

// ---------------- chunked selective scan --------------------------------------
#define CH 32

__global__ __launch_bounds__(128) void scan_pass1(
    const float* __restrict__ xdbl, float* __restrict__ dtraw,
    const float* __restrict__ dtb,
    const __nv_bfloat16* __restrict__ xc_hi, const __nv_bfloat16* __restrict__ xc_lo,
    const float* __restrict__ A_log,
    float* __restrict__ hend, float* __restrict__ Pbuf)
{
    const int b = blockIdx.z, c = blockIdx.y;
    const int d = blockIdx.x * 128 + threadIdx.x;
    float a[DS], h[DS];
    bool pow_ok = true;
    #pragma unroll
    for (int s = 0; s < DS; s++) {
        a[s] = -__expf(A_log[(size_t)d * DS + s]);
        pow_ok = pow_ok && (fabsf(-a[s] - (float)(s + 1)) < 1e-3f);
        h[s] = 0.f;
    }
    const float bias = dtb[d];
    float sumdt = 0.f;
    __shared__ float sB[CH][DS];
    const int tbase = c * CS;

    for (int t0 = 0; t0 < CS; t0 += CH) {
        __syncthreads();
        for (int idx = threadIdx.x; idx < CH * DS; idx += 128) {
            int r = idx >> 4, col = idx & 15;
            sB[r][col] = xdbl[(size_t)(b * LL + tbase + t0 + r) * NXD + DTRK + col];
        }
        __syncthreads();
        if (pow_ok) {
            #pragma unroll 4
            for (int r = 0; r < CH; r++) {
                size_t off = (size_t)(b * LL + tbase + t0 + r) * DIM + d;
                float dtv = softplus_f(dtraw[off] + bias);
                dtraw[off] = dtv;
                sumdt += dtv;
                float x = __bfloat162float(xc_hi[off]) + __bfloat162float(xc_lo[off]);
                float dtx = dtv * x;
                float pw[DS];
                pow_tree(__expf(-dtv), pw);
                #pragma unroll
                for (int s = 0; s < DS; s++)
                    h[s] = fmaf(pw[s], h[s], dtx * sB[r][s]);
            }
        } else {
            #pragma unroll 4
            for (int r = 0; r < CH; r++) {
                size_t off = (size_t)(b * LL + tbase + t0 + r) * DIM + d;
                float dtv = softplus_f(dtraw[off] + bias);
                dtraw[off] = dtv;
                sumdt += dtv;
                float x = __bfloat162float(xc_hi[off]) + __bfloat162float(xc_lo[off]);
                float dtx = dtv * x;
                #pragma unroll
                for (int s = 0; s < DS; s++)
                    h[s] = fmaf(__expf(dtv * a[s]), h[s], dtx * sB[r][s]);
            }
        }
    }
    size_t obase = ((size_t)(b * NC + c) * DS) * DIM + d;
    if (pow_ok) {
        float pw[DS];
        pow_tree(__expf(-sumdt), pw);
        #pragma unroll
        for (int s = 0; s < DS; s++) {
            hend[obase + (size_t)s * DIM] = h[s];
            Pbuf[obase + (size_t)s * DIM] = pw[s];
        }
    } else {
        #pragma unroll
        for (int s = 0; s < DS; s++) {
            hend[obase + (size_t)s * DIM] = h[s];
            Pbuf[obase + (size_t)s * DIM] = __expf(a[s] * sumdt);
        }
    }
}

__global__ __launch_bounds__(128) void scan_pass3(
    const float* __restrict__ xdbl, const float* __restrict__ dtv_buf,
    const __nv_bfloat16* __restrict__ xc_hi, const __nv_bfloat16* __restrict__ xc_lo,
    const float* __restrict__ xz,
    const float* __restrict__ A_log, const float* __restrict__ Dp,
    const float* __restrict__ hend, const float* __restrict__ Pbuf,
    __nv_bfloat16* __restrict__ y_hi, __nv_bfloat16* __restrict__ y_lo)
{
    const int b = blockIdx.z, c = blockIdx.y;
    const int d = blockIdx.x * 128 + threadIdx.x;
    float a[DS], h[DS];
    bool pow_ok = true;
    #pragma unroll
    for (int s = 0; s < DS; s++) {
        a[s] = -__expf(A_log[(size_t)d * DS + s]);
        pow_ok = pow_ok && (fabsf(-a[s] - (float)(s + 1)) < 1e-3f);
        h[s] = 0.f;
    }
    for (int cc = 0; cc < c; cc++) {
        size_t base = ((size_t)(b * NC + cc) * DS) * DIM + d;
        #pragma unroll
        for (int s = 0; s < DS; s++)
            h[s] = fmaf(Pbuf[base + (size_t)s * DIM], h[s],
                        hend[base + (size_t)s * DIM]);
    }
    const float Dd = Dp[d];
    __shared__ float sB[CH][DS];
    __shared__ float sC[CH][DS];
    const int tbase = c * CS;

    for (int t0 = 0; t0 < CS; t0 += CH) {
        __syncthreads();
        for (int idx = threadIdx.x; idx < CH * 32; idx += 128) {
            int r = idx >> 5, col = idx & 31;
            float v = xdbl[(size_t)(b * LL + tbase + t0 + r) * NXD + DTRK + col];
            if (col < DS) sB[r][col] = v; else sC[r][col - DS] = v;
        }
        __syncthreads();
        if (pow_ok) {
            #pragma unroll 4
            for (int r = 0; r < CH; r++) {
                int t = tbase + t0 + r;
                size_t off = (size_t)(b * LL + t) * DIM + d;
                float dtv = dtv_buf[off];
                float x = __bfloat162float(xc_hi[off]) + __bfloat162float(xc_lo[off]);
                float z = xz[(size_t)(b * LL + t) * (2 * DIM) + DIM + d];
                float dtx = dtv * x;
                float y = 0.f;
                float pw[DS];
                pow_tree(__expf(-dtv), pw);
                #pragma unroll
                for (int s = 0; s < DS; s++) {
                    h[s] = fmaf(pw[s], h[s], dtx * sB[r][s]);
                    y = fmaf(h[s], sC[r][s], y);
                }
                float sz = z / (1.f + __expf(-z));
                float yo = (y + Dd * x) * sz;
                __nv_bfloat16 hh, ll; split_bf16(yo, hh, ll);
                y_hi[off] = hh; y_lo[off] = ll;
            }
        } else {
            #pragma unroll 4
            for (int r = 0; r < CH; r++) {
                int t = tbase + t0 + r;
                size_t off = (size_t)(b * LL + t) * DIM + d;
                float dtv = dtv_buf[off];
                float x = __bfloat162float(xc_hi[off]) + __bfloat162float(xc_lo[off]);
                float z = xz[(size_t)(b * LL + t) * (2 * DIM) + DIM + d];
                float dtx = dtv * x;
                float y = 0.f;
                #pragma unroll
                for (int s = 0; s < DS; s++) {
                    h[s] = fmaf(__expf(dtv * a[s]), h[s], dtx * sB[r][s]);
                    y = fmaf(h[s], sC[r][s], y);
                }
                float sz = z / (1.f + __expf(-z));
                float yo = (y + Dd * x) * sz;
                __nv_bfloat16 hh, ll; split_bf16(yo, hh, ll);
                y_hi[off] = hh; y_lo[off] = ll;
            }
        }
    }
}

// ---------------- launch ------------------------------------------------------
extern "C" void kernel_launch(void* const* d_in, const int* in_sizes, int n_in,
                              void* d_out, int out_size)
{
    const float* x          = (const float*)d_in[0];
    const float* residual   = (const float*)d_in[1];
    const float* ln_w       = (const float*)d_in[2];
    const float* ln_b       = (const float*)d_in[3];
    const float* in_proj_w  = (const float*)d_in[4];
    const float* conv_w     = (const float*)d_in[5];
    const float* conv_b     = (const float*)d_in[6];
    const float* x_proj_w   = (const float*)d_in[7];
    const float* dt_proj_w  = (const float*)d_in[8];
    const float* dt_proj_b  = (const float*)d_in[9];
    const float* A_log      = (const float*)d_in[10];
    const float* D_param    = (const float*)d_in[11];
    const float* out_proj_w = (const float*)d_in[12];

    float* out     = (float*)d_out;
    float* res_out = out + (size_t)BL * DD;

    float *xz, *xdbl, *xpart, *dtraw, *hend, *Pbuf;
    __nv_bfloat16 *h_hi, *h_lo, *wi_hi, *wi_lo, *xc_hi, *xc_lo, *xp_hi, *xp_lo;
    __nv_bfloat16 *dta_hi, *dta_lo, *dtw_hi, *dtw_lo, *y_hi, *y_lo, *ow_hi, *ow_lo;
    cudaGetSymbolAddress((void**)&xz,    g_xz);
    cudaGetSymbolAddress((void**)&xdbl,  g_xdbl);
    cudaGetSymbolAddress((void**)&xpart, g_xpart);
    cudaGetSymbolAddress((void**)&dtraw, g_dtraw);
    cudaGetSymbolAddress((void**)&hend,  g_hend);
    cudaGetSymbolAddress((void**)&Pbuf,  g_P);
    cudaGetSymbolAddress((void**)&h_hi,  g_h_hi);  cudaGetSymbolAddress((void**)&h_lo,  g_h_lo);
    cudaGetSymbolAddress((void**)&wi_hi, g_wi_hi); cudaGetSymbolAddress((void**)&wi_lo, g_wi_lo);
    cudaGetSymbolAddress((void**)&xc_hi, g_xc_hi); cudaGetSymbolAddress((void**)&xc_lo, g_xc_lo);
    cudaGetSymbolAddress((void**)&xp_hi, g_xp_hi); cudaGetSymbolAddress((void**)&xp_lo, g_xp_lo);
    cudaGetSymbolAddress((void**)&dta_hi,g_dta_hi);cudaGetSymbolAddress((void**)&dta_lo,g_dta_lo);
    cudaGetSymbolAddress((void**)&dtw_hi,g_dtw_hi);cudaGetSymbolAddress((void**)&dtw_lo,g_dtw_lo);
    cudaGetSymbolAddress((void**)&y_hi,  g_y_hi);  cudaGetSymbolAddress((void**)&y_lo,  g_y_lo);
    cudaGetSymbolAddress((void**)&ow_hi, g_ow_hi); cudaGetSymbolAddress((void**)&ow_lo, g_ow_lo);

    cudaFuncSetAttribute(tc_gemm,  cudaFuncAttributeMaxDynamicSharedMemorySize, GSMEM);
    cudaFuncSetAttribute(tc_gemm2, cudaFuncAttributeMaxDynamicSharedMemorySize, GSMEM2);

    // 0) in_proj weight cvt
    {
        long t1 = (long)2 * DIM * DD;
        cvt_flat_kernel<<<(int)((t1 + 255) / 256), 256>>>(in_proj_w, t1, wi_hi, wi_lo);
    }
    // 1) remaining weights (fused)
    cvt_rest_kernel<<<(int)((C3 + 255) / 256), 256>>>(
        x_proj_w, dt_proj_w, out_proj_w,
        xp_hi, xp_lo, dtw_hi, dtw_lo, ow_hi, ow_lo);

    // 2) residual = x + residual; h = LN(residual) -> hi/lo
    addnorm_kernel<<<BL, 256>>>(x, residual, ln_w, ln_b, res_out, h_hi, h_lo);

    // 3) xz = h @ in_proj_w^T   (M=4096, N=4096, K=1024)   <-- ncu window
    tc_gemm2<<<dim3(2 * DIM / 256, BL / 128), 256, GSMEM2>>>(
        h_hi, h_lo, wi_hi, wi_lo, xz, 2 * DIM, DD);

    // 4) xc = silu(causal_conv(x_in)) -> hi/lo only
    conv_silu_kernel<<<(BB * LL * DIM + 255) / 256, 256>>>(xz, conv_w, conv_b, xc_hi, xc_lo);

    // 5) x_dbl = xc @ x_proj_w^T (M=4096, N=96, K=2048), 8-way split-K + reduce
    tc_gemm<<<dim3(1, BL / 128, KSPL), 256, GSMEM>>>(
        xc_hi, xc_lo, xp_hi, xp_lo, xpart, NXD, NXD, DIM, DIM / KSPL,
        (long)BL * NXD);
    xpart_reduce_kernel<<<(BL * NXD + 255) / 256, 256>>>(xpart, xdbl, dta_hi, dta_lo);

    // 6) dt_raw = dt_r @ dt_proj_w^T   (M=4096, N=2048, K=64)
    tc_gemm2<<<dim3(DIM / 256, BL / 128), 256, GSMEM2>>>(
        dta_hi, dta_lo, dtw_hi, dtw_lo, dtraw, DIM, DTRK);

    // 7) chunked selective scan
    scan_pass1<<<dim3(DIM / 128, NC, BB), 128>>>(
        xdbl, dtraw, dt_proj_b, xc_hi, xc_lo, A_log, hend, Pbuf);
    scan_pass3<<<dim3(DIM / 128, NC, BB), 128>>>(
        xdbl, dtraw, xc_hi, xc_lo, xz, A_log, D_param, hend, Pbuf, y_hi, y_lo);

    // 8) out = y @ out_proj_w^T   (M=4096, N=1024, K=2048)
    tc_gemm2<<<dim3(DD / 256, BL / 128), 256, GSMEM2>>>(
        y_hi, y_lo, ow_hi, ow_lo, out, DD, DIM);
}

// round 12
// speedup vs baseline: 1.1387x; 1.1387x over previous
#include <cuda_runtime.h>
#include <cuda_bf16.h>
#include <cstdint>
#include <math.h>

// Problem constants
#define BB   2
#define LL   2048
#define DD   1024
#define DIM  2048      // d_inner
#define DS   16        // d_state
#define DTRK 64        // dt_rank
#define NXD  96        // DTR + 2*DS
#define BL   (BB*LL)   // 4096 rows
#define NC   16        // scan chunks
#define CS   (LL/NC)   // 128 steps per chunk
#define KSPL 8         // x_proj split-K factor

// ---------------- scratch ----------------------------------------------------
__device__ __align__(256) float g_xz[(size_t)BL * 2 * DIM];
__device__ __align__(256) float g_xdbl[(size_t)BL * NXD];
__device__ __align__(256) float g_xpart[(size_t)KSPL * BL * NXD];
__device__ __align__(256) float g_dtraw[(size_t)BL * DIM];   // dt linear -> dtv (in-place)
__device__ __align__(256) float g_hend[(size_t)BB * NC * DS * DIM];
__device__ __align__(256) float g_P[(size_t)BB * NC * DS * DIM];

__device__ __align__(256) __nv_bfloat16 g_h_hi[(size_t)BL * DD],    g_h_lo[(size_t)BL * DD];
__device__ __align__(256) __nv_bfloat16 g_wi_hi[(size_t)2*DIM*DD],  g_wi_lo[(size_t)2*DIM*DD];
__device__ __align__(256) __nv_bfloat16 g_xc_hi[(size_t)BL * DIM],  g_xc_lo[(size_t)BL * DIM];
__device__ __align__(256) __nv_bfloat16 g_xp_hi[(size_t)NXD * DIM], g_xp_lo[(size_t)NXD * DIM];
__device__ __align__(256) __nv_bfloat16 g_dta_hi[(size_t)BL * DTRK],g_dta_lo[(size_t)BL * DTRK];
__device__ __align__(256) __nv_bfloat16 g_dtw_hi[(size_t)DIM*DTRK], g_dtw_lo[(size_t)DIM*DTRK];
__device__ __align__(256) __nv_bfloat16 g_y_hi[(size_t)BL * DIM],   g_y_lo[(size_t)BL * DIM];
__device__ __align__(256) __nv_bfloat16 g_ow_hi[(size_t)DD * DIM],  g_ow_lo[(size_t)DD * DIM];

// ---------------- helpers ----------------------------------------------------
__device__ __forceinline__ uint32_t smem_u32(const void* p) {
    uint32_t a;
    asm("{ .reg .u64 t; cvta.to.shared.u64 t, %1; cvt.u32.u64 %0, t; }"
        : "=r"(a) : "l"(p));
    return a;
}
__device__ __forceinline__ void split_bf16(float v, __nv_bfloat16& hi, __nv_bfloat16& lo) {
    hi = __float2bfloat16(v);
    lo = __float2bfloat16(v - __bfloat162float(hi));
}
__device__ __forceinline__ float softplus_f(float x) {
    return (x > 20.f) ? x : log1pf(__expf(x));
}
// powers E^1..E^16 via depth-4 tree
__device__ __forceinline__ void pow_tree(float E, float pw[DS]) {
    float E2 = E * E, E4 = E2 * E2, E8 = E4 * E4;
    pw[0] = E;        pw[1] = E2;       pw[2] = E2 * E;   pw[3] = E4;
    pw[4] = E4 * E;   pw[5] = E4 * E2;  pw[6] = E4 * pw[2]; pw[7] = E8;
    pw[8] = E8 * E;   pw[9] = E8 * E2;  pw[10] = E8 * pw[2]; pw[11] = E8 * E4;
    pw[12] = E8 * pw[4]; pw[13] = E8 * pw[5]; pw[14] = E8 * pw[6]; pw[15] = E8 * E8;
}

__device__ __forceinline__ void ldm_x4(uint32_t addr, uint32_t r[4]) {
    asm volatile("ldmatrix.sync.aligned.m8n8.x4.shared.b16 {%0,%1,%2,%3}, [%4];"
        : "=r"(r[0]), "=r"(r[1]), "=r"(r[2]), "=r"(r[3]) : "r"(addr));
}
__device__ __forceinline__ void mma_bf16(float d[4], const uint32_t a[4],
                                         uint32_t b0, uint32_t b1) {
    asm volatile(
        "mma.sync.aligned.m16n8k16.row.col.f32.bf16.bf16.f32 "
        "{%0,%1,%2,%3}, {%4,%5,%6,%7}, {%8,%9}, {%0,%1,%2,%3};"
        : "+f"(d[0]), "+f"(d[1]), "+f"(d[2]), "+f"(d[3])
        : "r"(a[0]), "r"(a[1]), "r"(a[2]), "r"(a[3]), "r"(b0), "r"(b1));
}
__device__ __forceinline__ void cp16(uint32_t dst, const void* src, int srcsize) {
    asm volatile("cp.async.cg.shared.global [%0], [%1], 16, %2;"
                 :: "r"(dst), "l"(src), "r"(srcsize));
}
__device__ __forceinline__ void cp_commit() {
    asm volatile("cp.async.commit_group;");
}
__device__ __forceinline__ void cp_wait2() {
    asm volatile("cp.async.wait_group 2;");
}

// ======== tc_gemm: 128x128 tile, 8 warps (4m x 2n), 2 CTA/SM, 3-stage ========
// Proven round-10 configuration. N-guarded; split-K via blockIdx.z.
#define TILEB 8192
#define STAGE3 (4 * TILEB)
#define GSMEM (3 * STAGE3)

__global__ __launch_bounds__(256, 2) void tc_gemm(
    const __nv_bfloat16* __restrict__ Ahi, const __nv_bfloat16* __restrict__ Alo,
    const __nv_bfloat16* __restrict__ Bhi, const __nv_bfloat16* __restrict__ Blo,
    float* __restrict__ C, int ldc, int N, int ldK, int Ksub, long cstride)
{
    extern __shared__ char smem[];
    const uint32_t sbase = smem_u32(smem);
    const int tid  = threadIdx.x;
    const int wid  = tid >> 5;
    const int lane = tid & 31;
    const int warp_m = wid & 3;
    const int warp_n = wid >> 2;
    const int m0 = blockIdx.y * 128;
    const int n0 = blockIdx.x * 128;
    const int kbase = blockIdx.z * Ksub;
    C += (long)blockIdx.z * cstride;

    const __nv_bfloat16* srcA[2] = { Ahi + (size_t)m0 * ldK + kbase,
                                     Alo + (size_t)m0 * ldK + kbase };
    const __nv_bfloat16* srcB[2] = { Bhi + (size_t)n0 * ldK + kbase,
                                     Blo + (size_t)n0 * ldK + kbase };

    float acc[2][8][4];
    #pragma unroll
    for (int a = 0; a < 2; a++)
        #pragma unroll
        for (int b = 0; b < 8; b++)
            #pragma unroll
            for (int c = 0; c < 4; c++) acc[a][b][c] = 0.f;

    const int nch = Ksub / 32;

    auto load_chunk = [&](int stage, int k0) {
        const uint32_t base = sbase + stage * STAGE3;
        #pragma unroll
        for (int i = 0; i < 8; i++) {
            const int tile = i >> 1;
            const int rem  = ((i & 1) << 8) + tid;
            const int row  = rem >> 2;
            const int c    = rem & 3;
            const int csw  = c ^ ((row >> 1) & 3);
            const uint32_t dst = base + tile * TILEB + row * 64 + csw * 16;
            const __nv_bfloat16* g;
            int sz = 16;
            if (tile < 2) {
                g = srcA[tile] + (size_t)row * ldK + k0 + c * 8;
            } else {
                g = srcB[tile - 2] + (size_t)row * ldK + k0 + c * 8;
                if (n0 + row >= N) sz = 0;
            }
            cp16(dst, g, sz);
        }
    };

    load_chunk(0, 0);
    cp_commit();
    if (1 < nch) load_chunk(1, 32);
    cp_commit();

    for (int ch = 0; ch < nch; ch++) {
        if (ch + 2 < nch) load_chunk((ch + 2) % 3, (ch + 2) * 32);
        cp_commit();
        cp_wait2();
        __syncthreads();

        const uint32_t st = sbase + (ch % 3) * STAGE3;
        const uint32_t aHiB = st;
        const uint32_t aLoB = st + TILEB;
        const uint32_t bHiB = st + 2 * TILEB;
        const uint32_t bLoB = st + 3 * TILEB;

        #pragma unroll
        for (int k16 = 0; k16 < 2; k16++) {
            uint32_t ah[2][4], al[2][4], bh[4][4], bl[4][4];
            const int ci = k16 * 2 + (lane >> 4);
            #pragma unroll
            for (int mf = 0; mf < 2; mf++) {
                const int row = warp_m * 32 + mf * 16 + (lane & 15);
                const uint32_t off = row * 64 + ((ci ^ ((row >> 1) & 3)) * 16);
                ldm_x4(aHiB + off, ah[mf]);
                ldm_x4(aLoB + off, al[mf]);
            }
            #pragma unroll
            for (int nb = 0; nb < 4; nb++) {
                const int rowb = warp_n * 64 + nb * 16 + (lane & 15);
                const uint32_t offb = rowb * 64 + ((ci ^ ((rowb >> 1) & 3)) * 16);
                ldm_x4(bHiB + offb, bh[nb]);
                ldm_x4(bLoB + offb, bl[nb]);
            }
            #pragma unroll
            for (int mf = 0; mf < 2; mf++)
                #pragma unroll
                for (int nb = 0; nb < 4; nb++) {
                    mma_bf16(acc[mf][nb*2],   ah[mf], bh[nb][0], bh[nb][2]);
                    mma_bf16(acc[mf][nb*2+1], ah[mf], bh[nb][1], bh[nb][3]);
                }
            #pragma unroll
            for (int mf = 0; mf < 2; mf++)
                #pragma unroll
                for (int nb = 0; nb < 4; nb++) {
                    mma_bf16(acc[mf][nb*2],   ah[mf], bl[nb][0], bl[nb][2]);
                    mma_bf16(acc[mf][nb*2+1], ah[mf], bl[nb][1], bl[nb][3]);
                }
            #pragma unroll
            for (int mf = 0; mf < 2; mf++)
                #pragma unroll
                for (int nb = 0; nb < 4; nb++) {
                    mma_bf16(acc[mf][nb*2],   al[mf], bh[nb][0], bh[nb][2]);
                    mma_bf16(acc[mf][nb*2+1], al[mf], bh[nb][1], bh[nb][3]);
                }
        }
        __syncthreads();
    }

    #pragma unroll
    for (int mf = 0; mf < 2; mf++) {
        #pragma unroll
        for (int nf = 0; nf < 8; nf++) {
            const int r0  = m0 + warp_m * 32 + mf * 16 + (lane >> 2);
            const int col = n0 + warp_n * 64 + nf * 8 + (lane & 3) * 2;
            if (col < N) {
                float2 v0 = make_float2(acc[mf][nf][0], acc[mf][nf][1]);
                float2 v1 = make_float2(acc[mf][nf][2], acc[mf][nf][3]);
                *reinterpret_cast<float2*>(C + (size_t)r0 * ldc + col) = v0;
                *reinterpret_cast<float2*>(C + (size_t)(r0 + 8) * ldc + col) = v1;
            }
        }
    }
}

// ---------------- split-K reduce for x_proj + fused dt-slice cvt -------------
__global__ __launch_bounds__(256) void xpart_reduce_kernel(
    const float* __restrict__ part, float* __restrict__ xdbl,
    __nv_bfloat16* __restrict__ dta_hi, __nv_bfloat16* __restrict__ dta_lo)
{
    int i = blockIdx.x * blockDim.x + threadIdx.x;
    if (i >= BL * NXD) return;
    float s = 0.f;
    #pragma unroll
    for (int z = 0; z < KSPL; z++) s += part[(size_t)z * BL * NXD + i];
    xdbl[i] = s;
    int col = i % NXD;
    if (col < DTRK) {
        int row = i / NXD;
        __nv_bfloat16 h, l; split_bf16(s, h, l);
        dta_hi[(size_t)row * DTRK + col] = h;
        dta_lo[(size_t)row * DTRK + col] = l;
    }
}

// ---------------- weight conversions ----------------------------------------
__global__ __launch_bounds__(256) void cvt_flat_kernel(
    const float* __restrict__ src, long total,
    __nv_bfloat16* __restrict__ hi, __nv_bfloat16* __restrict__ lo)
{
    long i = (long)blockIdx.x * blockDim.x + threadIdx.x;
    if (i >= total) return;
    __nv_bfloat16 h, l; split_bf16(src[i], h, l);
    hi[i] = h; lo[i] = l;
}

#define C1 ((long)NXD * DIM)
#define C2 (C1 + (long)DIM * DTRK)
#define C3 (C2 + (long)DD * DIM)
__global__ __launch_bounds__(256) void cvt_rest_kernel(
    const float* __restrict__ s0, const float* __restrict__ s1,
    const float* __restrict__ s2,
    __nv_bfloat16* __restrict__ h0, __nv_bfloat16* __restrict__ l0,
    __nv_bfloat16* __restrict__ h1, __nv_bfloat16* __restrict__ l1,
    __nv_bfloat16* __restrict__ h2, __nv_bfloat16* __restrict__ l2)
{
    long i = (long)blockIdx.x * blockDim.x + threadIdx.x;
    if (i >= C3) return;
    const float* s; __nv_bfloat16 *ph, *pl; long j;
    if (i < C1)      { s = s0; ph = h0; pl = l0; j = i; }
    else if (i < C2) { s = s1; ph = h1; pl = l1; j = i - C1; }
    else             { s = s2; ph = h2; pl = l2; j = i - C2; }
    __nv_bfloat16 h, l; split_bf16(s[j], h, l);
    ph[j] = h; pl[j] = l;
}

// ---------------- fused add + LayerNorm (emits residual + h hi/lo) ----------
__global__ __launch_bounds__(256) void addnorm_kernel(
    const float* __restrict__ x, const float* __restrict__ res,
    const float* __restrict__ w, const float* __restrict__ b,
    float* __restrict__ res_out,
    __nv_bfloat16* __restrict__ h_hi, __nv_bfloat16* __restrict__ h_lo)
{
    const int row = blockIdx.x;
    const int tid = threadIdx.x;
    const float4* xv = reinterpret_cast<const float4*>(x + (size_t)row * DD);
    const float4* rv = reinterpret_cast<const float4*>(res + (size_t)row * DD);
    float4 a = xv[tid], r = rv[tid];
    float4 v = make_float4(a.x + r.x, a.y + r.y, a.z + r.z, a.w + r.w);
    reinterpret_cast<float4*>(res_out + (size_t)row * DD)[tid] = v;

    float s  = v.x + v.y + v.z + v.w;
    float ss = v.x*v.x + v.y*v.y + v.z*v.z + v.w*v.w;
    __shared__ float red[16];
    #pragma unroll
    for (int o = 16; o > 0; o >>= 1) {
        s  += __shfl_xor_sync(0xFFFFFFFFu, s,  o);
        ss += __shfl_xor_sync(0xFFFFFFFFu, ss, o);
    }
    int wid = tid >> 5, lane = tid & 31;
    if (lane == 0) { red[wid] = s; red[8 + wid] = ss; }
    __syncthreads();
    if (tid == 0) {
        float ts = 0.f, tss = 0.f;
        #pragma unroll
        for (int i = 0; i < 8; i++) { ts += red[i]; tss += red[8 + i]; }
        float mean = ts * (1.f / DD);
        float var  = tss * (1.f / DD) - mean * mean;
        red[0] = mean; red[1] = rsqrtf(var + 1e-5f);
    }
    __syncthreads();
    float mean = red[0], rstd = red[1];
    float4 wv = reinterpret_cast<const float4*>(w)[tid];
    float4 bv = reinterpret_cast<const float4*>(b)[tid];
    float hv[4];
    hv[0] = (v.x - mean) * rstd * wv.x + bv.x;
    hv[1] = (v.y - mean) * rstd * wv.y + bv.y;
    hv[2] = (v.z - mean) * rstd * wv.z + bv.z;
    hv[3] = (v.w - mean) * rstd * wv.w + bv.w;
    __nv_bfloat16 hh[4], ll[4];
    #pragma unroll
    for (int i = 0; i < 4; i++) split_bf16(hv[i], hh[i], ll[i]);
    size_t o = (size_t)row * DD + tid * 4;
    *reinterpret_cast<uint2*>(h_hi + o) = *reinterpret_cast<uint2*>(hh);
    *reinterpret_cast<uint2*>(h_lo + o) = *reinterpret_cast<uint2*>(ll);
}

// ---------------- causal depthwise conv (DC=4) + SiLU (hi/lo only) -----------
__global__ __launch_bounds__(256) void conv_silu_kernel(
    const float* __restrict__ xz, const float* __restrict__ cw,
    const float* __restrict__ cb,
    __nv_bfloat16* __restrict__ xc_hi, __nv_bfloat16* __restrict__ xc_lo)
{
    int idx = blockIdx.x * blockDim.x + threadIdx.x;
    if (idx >= BB * LL * DIM) return;
    int d = idx % DIM;
    int t = (idx / DIM) % LL;
    int b = idx / (DIM * LL);
    float w0 = cw[d * 4 + 0], w1 = cw[d * 4 + 1];
    float w2 = cw[d * 4 + 2], w3 = cw[d * 4 + 3];
    size_t base = ((size_t)(b * LL + t)) * (2 * DIM) + d;
    float acc = cb[d];
    if (t >= 3) acc = fmaf(xz[base - 3 * (size_t)(2 * DIM)], w0, acc);
    if (t >= 2) acc = fmaf(xz[base - 2 * (size_t)(2 * DIM)], w1, acc);
    if (t >= 1) acc = fmaf(xz[base - 1 * (size_t)(2 * DIM)], w2, acc);
    acc = fmaf(xz[base], w3, acc);
    float sg = 1.f / (1.f + __expf(-acc));
    float v = acc * sg;
    __nv_bfloat16 h, l; split_bf16(v, h, l);
    xc_hi[idx] = h; xc_lo[idx] = l;
}

// ---------------- chunked selective scan --------------------------------------
#define CH 32

__global__ __launch_bounds__(128) void scan_pass1(
    const float* __restrict__ xdbl, float* __restrict__ dtraw,
    const float* __restrict__ dtb,
    const __nv_bfloat16* __restrict__ xc_hi, const __nv_bfloat16* __restrict__ xc_lo,
    const float* __restrict__ A_log,
    float* __restrict__ hend, float* __restrict__ Pbuf)
{
    const int b = blockIdx.z, c = blockIdx.y;
    const int d = blockIdx.x * 128 + threadIdx.x;
    float a[DS], h[DS];
    bool pow_ok = true;
    #pragma unroll
    for (int s = 0; s < DS; s++) {
        a[s] = -__expf(A_log[(size_t)d * DS + s]);
        pow_ok = pow_ok && (fabsf(-a[s] - (float)(s + 1)) < 1e-3f);
        h[s] = 0.f;
    }
    const float bias = dtb[d];
    float sumdt = 0.f;
    __shared__ float sB[CH][DS];
    const int tbase = c * CS;

    for (int t0 = 0; t0 < CS; t0 += CH) {
        __syncthreads();
        for (int idx = threadIdx.x; idx < CH * DS; idx += 128) {
            int r = idx >> 4, col = idx & 15;
            sB[r][col] = xdbl[(size_t)(b * LL + tbase + t0 + r) * NXD + DTRK + col];
        }
        __syncthreads();
        if (pow_ok) {
            #pragma unroll 4
            for (int r = 0; r < CH; r++) {
                size_t off = (size_t)(b * LL + tbase + t0 + r) * DIM + d;
                float dtv = softplus_f(dtraw[off] + bias);
                dtraw[off] = dtv;
                sumdt += dtv;
                float x = __bfloat162float(xc_hi[off]) + __bfloat162float(xc_lo[off]);
                float dtx = dtv * x;
                float pw[DS];
                pow_tree(__expf(-dtv), pw);
                #pragma unroll
                for (int s = 0; s < DS; s++)
                    h[s] = fmaf(pw[s], h[s], dtx * sB[r][s]);
            }
        } else {
            #pragma unroll 4
            for (int r = 0; r < CH; r++) {
                size_t off = (size_t)(b * LL + tbase + t0 + r) * DIM + d;
                float dtv = softplus_f(dtraw[off] + bias);
                dtraw[off] = dtv;
                sumdt += dtv;
                float x = __bfloat162float(xc_hi[off]) + __bfloat162float(xc_lo[off]);
                float dtx = dtv * x;
                #pragma unroll
                for (int s = 0; s < DS; s++)
                    h[s] = fmaf(__expf(dtv * a[s]), h[s], dtx * sB[r][s]);
            }
        }
    }
    size_t obase = ((size_t)(b * NC + c) * DS) * DIM + d;
    if (pow_ok) {
        float pw[DS];
        pow_tree(__expf(-sumdt), pw);
        #pragma unroll
        for (int s = 0; s < DS; s++) {
            hend[obase + (size_t)s * DIM] = h[s];
            Pbuf[obase + (size_t)s * DIM] = pw[s];
        }
    } else {
        #pragma unroll
        for (int s = 0; s < DS; s++) {
            hend[obase + (size_t)s * DIM] = h[s];
            Pbuf[obase + (size_t)s * DIM] = __expf(a[s] * sumdt);
        }
    }
}

__global__ __launch_bounds__(128) void scan_pass3(
    const float* __restrict__ xdbl, const float* __restrict__ dtv_buf,
    const __nv_bfloat16* __restrict__ xc_hi, const __nv_bfloat16* __restrict__ xc_lo,
    const float* __restrict__ xz,
    const float* __restrict__ A_log, const float* __restrict__ Dp,
    const float* __restrict__ hend, const float* __restrict__ Pbuf,
    __nv_bfloat16* __restrict__ y_hi, __nv_bfloat16* __restrict__ y_lo)
{
    const int b = blockIdx.z, c = blockIdx.y;
    const int d = blockIdx.x * 128 + threadIdx.x;
    float a[DS], h[DS];
    bool pow_ok = true;
    #pragma unroll
    for (int s = 0; s < DS; s++) {
        a[s] = -__expf(A_log[(size_t)d * DS + s]);
        pow_ok = pow_ok && (fabsf(-a[s] - (float)(s + 1)) < 1e-3f);
        h[s] = 0.f;
    }
    for (int cc = 0; cc < c; cc++) {
        size_t base = ((size_t)(b * NC + cc) * DS) * DIM + d;
        #pragma unroll
        for (int s = 0; s < DS; s++)
            h[s] = fmaf(Pbuf[base + (size_t)s * DIM], h[s],
                        hend[base + (size_t)s * DIM]);
    }
    const float Dd = Dp[d];
    __shared__ float sB[CH][DS];
    __shared__ float sC[CH][DS];
    const int tbase = c * CS;

    for (int t0 = 0; t0 < CS; t0 += CH) {
        __syncthreads();
        for (int idx = threadIdx.x; idx < CH * 32; idx += 128) {
            int r = idx >> 5, col = idx & 31;
            float v = xdbl[(size_t)(b * LL + tbase + t0 + r) * NXD + DTRK + col];
            if (col < DS) sB[r][col] = v; else sC[r][col - DS] = v;
        }
        __syncthreads();
        if (pow_ok) {
            #pragma unroll 4
            for (int r = 0; r < CH; r++) {
                int t = tbase + t0 + r;
                size_t off = (size_t)(b * LL + t) * DIM + d;
                float dtv = dtv_buf[off];
                float x = __bfloat162float(xc_hi[off]) + __bfloat162float(xc_lo[off]);
                float z = xz[(size_t)(b * LL + t) * (2 * DIM) + DIM + d];
                float dtx = dtv * x;
                float y = 0.f;
                float pw[DS];
                pow_tree(__expf(-dtv), pw);
                #pragma unroll
                for (int s = 0; s < DS; s++) {
                    h[s] = fmaf(pw[s], h[s], dtx * sB[r][s]);
                    y = fmaf(h[s], sC[r][s], y);
                }
                float sz = z / (1.f + __expf(-z));
                float yo = (y + Dd * x) * sz;
                __nv_bfloat16 hh, ll; split_bf16(yo, hh, ll);
                y_hi[off] = hh; y_lo[off] = ll;
            }
        } else {
            #pragma unroll 4
            for (int r = 0; r < CH; r++) {
                int t = tbase + t0 + r;
                size_t off = (size_t)(b * LL + t) * DIM + d;
                float dtv = dtv_buf[off];
                float x = __bfloat162float(xc_hi[off]) + __bfloat162float(xc_lo[off]);
                float z = xz[(size_t)(b * LL + t) * (2 * DIM) + DIM + d];
                float dtx = dtv * x;
                float y = 0.f;
                #pragma unroll
                for (int s = 0; s < DS; s++) {
                    h[s] = fmaf(__expf(dtv * a[s]), h[s], dtx * sB[r][s]);
                    y = fmaf(h[s], sC[r][s], y);
                }
                float sz = z / (1.f + __expf(-z));
                float yo = (y + Dd * x) * sz;
                __nv_bfloat16 hh, ll; split_bf16(yo, hh, ll);
                y_hi[off] = hh; y_lo[off] = ll;
            }
        }
    }
}

// ---------------- launch ------------------------------------------------------
extern "C" void kernel_launch(void* const* d_in, const int* in_sizes, int n_in,
                              void* d_out, int out_size)
{
    const float* x          = (const float*)d_in[0];
    const float* residual   = (const float*)d_in[1];
    const float* ln_w       = (const float*)d_in[2];
    const float* ln_b       = (const float*)d_in[3];
    const float* in_proj_w  = (const float*)d_in[4];
    const float* conv_w     = (const float*)d_in[5];
    const float* conv_b     = (const float*)d_in[6];
    const float* x_proj_w   = (const float*)d_in[7];
    const float* dt_proj_w  = (const float*)d_in[8];
    const float* dt_proj_b  = (const float*)d_in[9];
    const float* A_log      = (const float*)d_in[10];
    const float* D_param    = (const float*)d_in[11];
    const float* out_proj_w = (const float*)d_in[12];

    float* out     = (float*)d_out;
    float* res_out = out + (size_t)BL * DD;

    float *xz, *xdbl, *xpart, *dtraw, *hend, *Pbuf;
    __nv_bfloat16 *h_hi, *h_lo, *wi_hi, *wi_lo, *xc_hi, *xc_lo, *xp_hi, *xp_lo;
    __nv_bfloat16 *dta_hi, *dta_lo, *dtw_hi, *dtw_lo, *y_hi, *y_lo, *ow_hi, *ow_lo;
    cudaGetSymbolAddress((void**)&xz,    g_xz);
    cudaGetSymbolAddress((void**)&xdbl,  g_xdbl);
    cudaGetSymbolAddress((void**)&xpart, g_xpart);
    cudaGetSymbolAddress((void**)&dtraw, g_dtraw);
    cudaGetSymbolAddress((void**)&hend,  g_hend);
    cudaGetSymbolAddress((void**)&Pbuf,  g_P);
    cudaGetSymbolAddress((void**)&h_hi,  g_h_hi);  cudaGetSymbolAddress((void**)&h_lo,  g_h_lo);
    cudaGetSymbolAddress((void**)&wi_hi, g_wi_hi); cudaGetSymbolAddress((void**)&wi_lo, g_wi_lo);
    cudaGetSymbolAddress((void**)&xc_hi, g_xc_hi); cudaGetSymbolAddress((void**)&xc_lo, g_xc_lo);
    cudaGetSymbolAddress((void**)&xp_hi, g_xp_hi); cudaGetSymbolAddress((void**)&xp_lo, g_xp_lo);
    cudaGetSymbolAddress((void**)&dta_hi,g_dta_hi);cudaGetSymbolAddress((void**)&dta_lo,g_dta_lo);
    cudaGetSymbolAddress((void**)&dtw_hi,g_dtw_hi);cudaGetSymbolAddress((void**)&dtw_lo,g_dtw_lo);
    cudaGetSymbolAddress((void**)&y_hi,  g_y_hi);  cudaGetSymbolAddress((void**)&y_lo,  g_y_lo);
    cudaGetSymbolAddress((void**)&ow_hi, g_ow_hi); cudaGetSymbolAddress((void**)&ow_lo, g_ow_lo);

    cudaFuncSetAttribute(tc_gemm, cudaFuncAttributeMaxDynamicSharedMemorySize, GSMEM);

    // 0) in_proj weight cvt
    {
        long t1 = (long)2 * DIM * DD;
        cvt_flat_kernel<<<(int)((t1 + 255) / 256), 256>>>(in_proj_w, t1, wi_hi, wi_lo);
    }
    // 1) remaining weights (fused)
    cvt_rest_kernel<<<(int)((C3 + 255) / 256), 256>>>(
        x_proj_w, dt_proj_w, out_proj_w,
        xp_hi, xp_lo, dtw_hi, dtw_lo, ow_hi, ow_lo);

    // 2) residual = x + residual; h = LN(residual) -> hi/lo
    addnorm_kernel<<<BL, 256>>>(x, residual, ln_w, ln_b, res_out, h_hi, h_lo);

    // 3) xz = h @ in_proj_w^T   (M=4096, N=4096, K=1024)   <-- ncu window
    tc_gemm<<<dim3(2 * DIM / 128, BL / 128), 256, GSMEM>>>(
        h_hi, h_lo, wi_hi, wi_lo, xz, 2 * DIM, 2 * DIM, DD, DD, 0);

    // 4) xc = silu(causal_conv(x_in)) -> hi/lo only
    conv_silu_kernel<<<(BB * LL * DIM + 255) / 256, 256>>>(xz, conv_w, conv_b, xc_hi, xc_lo);

    // 5) x_dbl = xc @ x_proj_w^T (M=4096, N=96, K=2048), 8-way split-K + reduce
    tc_gemm<<<dim3(1, BL / 128, KSPL), 256, GSMEM>>>(
        xc_hi, xc_lo, xp_hi, xp_lo, xpart, NXD, NXD, DIM, DIM / KSPL,
        (long)BL * NXD);
    xpart_reduce_kernel<<<(BL * NXD + 255) / 256, 256>>>(xpart, xdbl, dta_hi, dta_lo);

    // 6) dt_raw = dt_r @ dt_proj_w^T   (M=4096, N=2048, K=64)
    tc_gemm<<<dim3(DIM / 128, BL / 128), 256, GSMEM>>>(
        dta_hi, dta_lo, dtw_hi, dtw_lo, dtraw, DIM, DIM, DTRK, DTRK, 0);

    // 7) chunked selective scan
    scan_pass1<<<dim3(DIM / 128, NC, BB), 128>>>(
        xdbl, dtraw, dt_proj_b, xc_hi, xc_lo, A_log, hend, Pbuf);
    scan_pass3<<<dim3(DIM / 128, NC, BB), 128>>>(
        xdbl, dtraw, xc_hi, xc_lo, xz, A_log, D_param, hend, Pbuf, y_hi, y_lo);

    // 8) out = y @ out_proj_w^T   (M=4096, N=1024, K=2048)
    tc_gemm<<<dim3(DD / 128, BL / 128), 256, GSMEM>>>(
        y_hi, y_lo, ow_hi, ow_lo, out, DD, DD, DIM, DIM, 0);
}

// round 13
// speedup vs baseline: 1.1867x; 1.0422x over previous
#include <cuda_runtime.h>
#include <cuda_bf16.h>
#include <cstdint>
#include <math.h>

// Problem constants
#define BB   2
#define LL   2048
#define DD   1024
#define DIM  2048      // d_inner
#define DS   16        // d_state
#define DTRK 64        // dt_rank
#define NXD  96        // DTR + 2*DS
#define BL   (BB*LL)   // 4096 rows
#define NC   16        // scan chunks
#define CS   (LL/NC)   // 128 steps per chunk
#define KSPL 8         // x_proj split-K factor

// ---------------- scratch ----------------------------------------------------
__device__ __align__(256) float g_xz[(size_t)BL * 2 * DIM];
__device__ __align__(256) float g_xdbl[(size_t)BL * NXD];
__device__ __align__(256) float g_xpart[(size_t)KSPL * BL * NXD];
__device__ __align__(256) float g_dtv[(size_t)BL * DIM];     // softplus'd dt (from GEMM epi)
__device__ __align__(256) float g_hend[(size_t)BB * NC * DS * DIM];
__device__ __align__(256) float g_P[(size_t)BB * NC * DS * DIM];

__device__ __align__(256) __nv_bfloat16 g_h_hi[(size_t)BL * DD],    g_h_lo[(size_t)BL * DD];
__device__ __align__(256) __nv_bfloat16 g_wi_hi[(size_t)2*DIM*DD],  g_wi_lo[(size_t)2*DIM*DD];
__device__ __align__(256) __nv_bfloat16 g_xc_hi[(size_t)BL * DIM],  g_xc_lo[(size_t)BL * DIM];
__device__ __align__(256) __nv_bfloat16 g_xp_hi[(size_t)NXD * DIM], g_xp_lo[(size_t)NXD * DIM];
__device__ __align__(256) __nv_bfloat16 g_dta_hi[(size_t)BL * DTRK],g_dta_lo[(size_t)BL * DTRK];
__device__ __align__(256) __nv_bfloat16 g_dtw_hi[(size_t)DIM*DTRK], g_dtw_lo[(size_t)DIM*DTRK];
__device__ __align__(256) __nv_bfloat16 g_y_hi[(size_t)BL * DIM],   g_y_lo[(size_t)BL * DIM];
__device__ __align__(256) __nv_bfloat16 g_ow_hi[(size_t)DD * DIM],  g_ow_lo[(size_t)DD * DIM];

// ---------------- helpers ----------------------------------------------------
__device__ __forceinline__ uint32_t smem_u32(const void* p) {
    uint32_t a;
    asm("{ .reg .u64 t; cvta.to.shared.u64 t, %1; cvt.u32.u64 %0, t; }"
        : "=r"(a) : "l"(p));
    return a;
}
__device__ __forceinline__ void split_bf16(float v, __nv_bfloat16& hi, __nv_bfloat16& lo) {
    hi = __float2bfloat16(v);
    lo = __float2bfloat16(v - __bfloat162float(hi));
}
__device__ __forceinline__ float softplus_f(float x) {
    return (x > 20.f) ? x : log1pf(__expf(x));
}
// powers E^1..E^16 via depth-4 tree
__device__ __forceinline__ void pow_tree(float E, float pw[DS]) {
    float E2 = E * E, E4 = E2 * E2, E8 = E4 * E4;
    pw[0] = E;        pw[1] = E2;       pw[2] = E2 * E;   pw[3] = E4;
    pw[4] = E4 * E;   pw[5] = E4 * E2;  pw[6] = E4 * pw[2]; pw[7] = E8;
    pw[8] = E8 * E;   pw[9] = E8 * E2;  pw[10] = E8 * pw[2]; pw[11] = E8 * E4;
    pw[12] = E8 * pw[4]; pw[13] = E8 * pw[5]; pw[14] = E8 * pw[6]; pw[15] = E8 * E8;
}

__device__ __forceinline__ void ldm_x4(uint32_t addr, uint32_t r[4]) {
    asm volatile("ldmatrix.sync.aligned.m8n8.x4.shared.b16 {%0,%1,%2,%3}, [%4];"
        : "=r"(r[0]), "=r"(r[1]), "=r"(r[2]), "=r"(r[3]) : "r"(addr));
}
__device__ __forceinline__ void mma_bf16(float d[4], const uint32_t a[4],
                                         uint32_t b0, uint32_t b1) {
    asm volatile(
        "mma.sync.aligned.m16n8k16.row.col.f32.bf16.bf16.f32 "
        "{%0,%1,%2,%3}, {%4,%5,%6,%7}, {%8,%9}, {%0,%1,%2,%3};"
        : "+f"(d[0]), "+f"(d[1]), "+f"(d[2]), "+f"(d[3])
        : "r"(a[0]), "r"(a[1]), "r"(a[2]), "r"(a[3]), "r"(b0), "r"(b1));
}
__device__ __forceinline__ void cp16(uint32_t dst, const void* src, int srcsize) {
    asm volatile("cp.async.cg.shared.global [%0], [%1], 16, %2;"
                 :: "r"(dst), "l"(src), "r"(srcsize));
}
__device__ __forceinline__ void cp_commit() {
    asm volatile("cp.async.commit_group;");
}
__device__ __forceinline__ void cp_wait2() {
    asm volatile("cp.async.wait_group 2;");
}

// ======== tc_gemm: 128x128 tile, 8 warps (4m x 2n), 2 CTA/SM, 3-stage ========
// N-guarded; split-K via blockIdx.z; optional fused col-bias + softplus epilogue.
#define TILEB 8192
#define STAGE3 (4 * TILEB)
#define GSMEM (3 * STAGE3)

__global__ __launch_bounds__(256, 2) void tc_gemm(
    const __nv_bfloat16* __restrict__ Ahi, const __nv_bfloat16* __restrict__ Alo,
    const __nv_bfloat16* __restrict__ Bhi, const __nv_bfloat16* __restrict__ Blo,
    float* __restrict__ C, int ldc, int N, int ldK, int Ksub, long cstride,
    const float* __restrict__ bias)   // if non-null: C = softplus(acc + bias[col])
{
    extern __shared__ char smem[];
    const uint32_t sbase = smem_u32(smem);
    const int tid  = threadIdx.x;
    const int wid  = tid >> 5;
    const int lane = tid & 31;
    const int warp_m = wid & 3;
    const int warp_n = wid >> 2;
    const int m0 = blockIdx.y * 128;
    const int n0 = blockIdx.x * 128;
    const int kbase = blockIdx.z * Ksub;
    C += (long)blockIdx.z * cstride;

    const __nv_bfloat16* srcA[2] = { Ahi + (size_t)m0 * ldK + kbase,
                                     Alo + (size_t)m0 * ldK + kbase };
    const __nv_bfloat16* srcB[2] = { Bhi + (size_t)n0 * ldK + kbase,
                                     Blo + (size_t)n0 * ldK + kbase };

    float acc[2][8][4];
    #pragma unroll
    for (int a = 0; a < 2; a++)
        #pragma unroll
        for (int b = 0; b < 8; b++)
            #pragma unroll
            for (int c = 0; c < 4; c++) acc[a][b][c] = 0.f;

    const int nch = Ksub / 32;

    auto load_chunk = [&](int stage, int k0) {
        const uint32_t base = sbase + stage * STAGE3;
        #pragma unroll
        for (int i = 0; i < 8; i++) {
            const int tile = i >> 1;
            const int rem  = ((i & 1) << 8) + tid;
            const int row  = rem >> 2;
            const int c    = rem & 3;
            const int csw  = c ^ ((row >> 1) & 3);
            const uint32_t dst = base + tile * TILEB + row * 64 + csw * 16;
            const __nv_bfloat16* g;
            int sz = 16;
            if (tile < 2) {
                g = srcA[tile] + (size_t)row * ldK + k0 + c * 8;
            } else {
                g = srcB[tile - 2] + (size_t)row * ldK + k0 + c * 8;
                if (n0 + row >= N) sz = 0;
            }
            cp16(dst, g, sz);
        }
    };

    load_chunk(0, 0);
    cp_commit();
    if (1 < nch) load_chunk(1, 32);
    cp_commit();

    for (int ch = 0; ch < nch; ch++) {
        if (ch + 2 < nch) load_chunk((ch + 2) % 3, (ch + 2) * 32);
        cp_commit();
        cp_wait2();
        __syncthreads();

        const uint32_t st = sbase + (ch % 3) * STAGE3;
        const uint32_t aHiB = st;
        const uint32_t aLoB = st + TILEB;
        const uint32_t bHiB = st + 2 * TILEB;
        const uint32_t bLoB = st + 3 * TILEB;

        #pragma unroll
        for (int k16 = 0; k16 < 2; k16++) {
            uint32_t ah[2][4], al[2][4], bh[4][4], bl[4][4];
            const int ci = k16 * 2 + (lane >> 4);
            #pragma unroll
            for (int mf = 0; mf < 2; mf++) {
                const int row = warp_m * 32 + mf * 16 + (lane & 15);
                const uint32_t off = row * 64 + ((ci ^ ((row >> 1) & 3)) * 16);
                ldm_x4(aHiB + off, ah[mf]);
                ldm_x4(aLoB + off, al[mf]);
            }
            #pragma unroll
            for (int nb = 0; nb < 4; nb++) {
                const int rowb = warp_n * 64 + nb * 16 + (lane & 15);
                const uint32_t offb = rowb * 64 + ((ci ^ ((rowb >> 1) & 3)) * 16);
                ldm_x4(bHiB + offb, bh[nb]);
                ldm_x4(bLoB + offb, bl[nb]);
            }
            #pragma unroll
            for (int mf = 0; mf < 2; mf++)
                #pragma unroll
                for (int nb = 0; nb < 4; nb++) {
                    mma_bf16(acc[mf][nb*2],   ah[mf], bh[nb][0], bh[nb][2]);
                    mma_bf16(acc[mf][nb*2+1], ah[mf], bh[nb][1], bh[nb][3]);
                }
            #pragma unroll
            for (int mf = 0; mf < 2; mf++)
                #pragma unroll
                for (int nb = 0; nb < 4; nb++) {
                    mma_bf16(acc[mf][nb*2],   ah[mf], bl[nb][0], bl[nb][2]);
                    mma_bf16(acc[mf][nb*2+1], ah[mf], bl[nb][1], bl[nb][3]);
                }
            #pragma unroll
            for (int mf = 0; mf < 2; mf++)
                #pragma unroll
                for (int nb = 0; nb < 4; nb++) {
                    mma_bf16(acc[mf][nb*2],   al[mf], bh[nb][0], bh[nb][2]);
                    mma_bf16(acc[mf][nb*2+1], al[mf], bh[nb][1], bh[nb][3]);
                }
        }
        __syncthreads();
    }

    #pragma unroll
    for (int mf = 0; mf < 2; mf++) {
        #pragma unroll
        for (int nf = 0; nf < 8; nf++) {
            const int r0  = m0 + warp_m * 32 + mf * 16 + (lane >> 2);
            const int col = n0 + warp_n * 64 + nf * 8 + (lane & 3) * 2;
            if (col < N) {
                float2 v0 = make_float2(acc[mf][nf][0], acc[mf][nf][1]);
                float2 v1 = make_float2(acc[mf][nf][2], acc[mf][nf][3]);
                if (bias) {
                    float b0 = bias[col], b1 = bias[col + 1];
                    v0.x = softplus_f(v0.x + b0); v0.y = softplus_f(v0.y + b1);
                    v1.x = softplus_f(v1.x + b0); v1.y = softplus_f(v1.y + b1);
                }
                *reinterpret_cast<float2*>(C + (size_t)r0 * ldc + col) = v0;
                *reinterpret_cast<float2*>(C + (size_t)(r0 + 8) * ldc + col) = v1;
            }
        }
    }
}

// ---------------- split-K reduce for x_proj + fused dt-slice cvt -------------
__global__ __launch_bounds__(256) void xpart_reduce_kernel(
    const float* __restrict__ part, float* __restrict__ xdbl,
    __nv_bfloat16* __restrict__ dta_hi, __nv_bfloat16* __restrict__ dta_lo)
{
    int i = blockIdx.x * blockDim.x + threadIdx.x;
    if (i >= BL * NXD) return;
    float s = 0.f;
    #pragma unroll
    for (int z = 0; z < KSPL; z++) s += part[(size_t)z * BL * NXD + i];
    xdbl[i] = s;
    int col = i % NXD;
    if (col < DTRK) {
        int row = i / NXD;
        __nv_bfloat16 h, l; split_bf16(s, h, l);
        dta_hi[(size_t)row * DTRK + col] = h;
        dta_lo[(size_t)row * DTRK + col] = l;
    }
}

// ---------------- weight conversions ----------------------------------------
__global__ __launch_bounds__(256) void cvt_flat_kernel(
    const float* __restrict__ src, long total,
    __nv_bfloat16* __restrict__ hi, __nv_bfloat16* __restrict__ lo)
{
    long i = (long)blockIdx.x * blockDim.x + threadIdx.x;
    if (i >= total) return;
    __nv_bfloat16 h, l; split_bf16(src[i], h, l);
    hi[i] = h; lo[i] = l;
}

#define C1 ((long)NXD * DIM)
#define C2 (C1 + (long)DIM * DTRK)
#define C3 (C2 + (long)DD * DIM)
__global__ __launch_bounds__(256) void cvt_rest_kernel(
    const float* __restrict__ s0, const float* __restrict__ s1,
    const float* __restrict__ s2,
    __nv_bfloat16* __restrict__ h0, __nv_bfloat16* __restrict__ l0,
    __nv_bfloat16* __restrict__ h1, __nv_bfloat16* __restrict__ l1,
    __nv_bfloat16* __restrict__ h2, __nv_bfloat16* __restrict__ l2)
{
    long i = (long)blockIdx.x * blockDim.x + threadIdx.x;
    if (i >= C3) return;
    const float* s; __nv_bfloat16 *ph, *pl; long j;
    if (i < C1)      { s = s0; ph = h0; pl = l0; j = i; }
    else if (i < C2) { s = s1; ph = h1; pl = l1; j = i - C1; }
    else             { s = s2; ph = h2; pl = l2; j = i - C2; }
    __nv_bfloat16 h, l; split_bf16(s[j], h, l);
    ph[j] = h; pl[j] = l;
}

// ---------------- fused add + LayerNorm (emits residual + h hi/lo) ----------
__global__ __launch_bounds__(256) void addnorm_kernel(
    const float* __restrict__ x, const float* __restrict__ res,
    const float* __restrict__ w, const float* __restrict__ b,
    float* __restrict__ res_out,
    __nv_bfloat16* __restrict__ h_hi, __nv_bfloat16* __restrict__ h_lo)
{
    const int row = blockIdx.x;
    const int tid = threadIdx.x;
    const float4* xv = reinterpret_cast<const float4*>(x + (size_t)row * DD);
    const float4* rv = reinterpret_cast<const float4*>(res + (size_t)row * DD);
    float4 a = xv[tid], r = rv[tid];
    float4 v = make_float4(a.x + r.x, a.y + r.y, a.z + r.z, a.w + r.w);
    reinterpret_cast<float4*>(res_out + (size_t)row * DD)[tid] = v;

    float s  = v.x + v.y + v.z + v.w;
    float ss = v.x*v.x + v.y*v.y + v.z*v.z + v.w*v.w;
    __shared__ float red[16];
    #pragma unroll
    for (int o = 16; o > 0; o >>= 1) {
        s  += __shfl_xor_sync(0xFFFFFFFFu, s,  o);
        ss += __shfl_xor_sync(0xFFFFFFFFu, ss, o);
    }
    int wid = tid >> 5, lane = tid & 31;
    if (lane == 0) { red[wid] = s; red[8 + wid] = ss; }
    __syncthreads();
    if (tid == 0) {
        float ts = 0.f, tss = 0.f;
        #pragma unroll
        for (int i = 0; i < 8; i++) { ts += red[i]; tss += red[8 + i]; }
        float mean = ts * (1.f / DD);
        float var  = tss * (1.f / DD) - mean * mean;
        red[0] = mean; red[1] = rsqrtf(var + 1e-5f);
    }
    __syncthreads();
    float mean = red[0], rstd = red[1];
    float4 wv = reinterpret_cast<const float4*>(w)[tid];
    float4 bv = reinterpret_cast<const float4*>(b)[tid];
    float hv[4];
    hv[0] = (v.x - mean) * rstd * wv.x + bv.x;
    hv[1] = (v.y - mean) * rstd * wv.y + bv.y;
    hv[2] = (v.z - mean) * rstd * wv.z + bv.z;
    hv[3] = (v.w - mean) * rstd * wv.w + bv.w;
    __nv_bfloat16 hh[4], ll[4];
    #pragma unroll
    for (int i = 0; i < 4; i++) split_bf16(hv[i], hh[i], ll[i]);
    size_t o = (size_t)row * DD + tid * 4;
    *reinterpret_cast<uint2*>(h_hi + o) = *reinterpret_cast<uint2*>(hh);
    *reinterpret_cast<uint2*>(h_lo + o) = *reinterpret_cast<uint2*>(ll);
}

// ---------------- causal depthwise conv (DC=4) + SiLU, x4 vectorized ---------
__global__ __launch_bounds__(256) void conv_silu_kernel(
    const float* __restrict__ xz, const float* __restrict__ cw,
    const float* __restrict__ cb,
    __nv_bfloat16* __restrict__ xc_hi, __nv_bfloat16* __restrict__ xc_lo)
{
    int idx = blockIdx.x * blockDim.x + threadIdx.x;   // over BB*LL*DIM/4
    if (idx >= BB * LL * (DIM / 4)) return;
    int d4 = (idx % (DIM / 4)) * 4;
    int t  = (idx / (DIM / 4)) % LL;
    int b  = idx / ((DIM / 4) * LL);

    const float4* cw4 = reinterpret_cast<const float4*>(cw);   // [DIM] of 4 taps
    float4 tp0 = cw4[d4 + 0], tp1 = cw4[d4 + 1];
    float4 tp2 = cw4[d4 + 2], tp3 = cw4[d4 + 3];

    size_t base = ((size_t)(b * LL + t)) * (2 * DIM) + d4;
    const size_t RS = 2 * DIM;
    float4 zero = make_float4(0.f, 0.f, 0.f, 0.f);
    float4 x0 = *reinterpret_cast<const float4*>(xz + base);
    float4 x1 = (t >= 1) ? *reinterpret_cast<const float4*>(xz + base - RS)     : zero;
    float4 x2 = (t >= 2) ? *reinterpret_cast<const float4*>(xz + base - 2 * RS) : zero;
    float4 x3 = (t >= 3) ? *reinterpret_cast<const float4*>(xz + base - 3 * RS) : zero;

    float4 cbv = *reinterpret_cast<const float4*>(cb + d4);
    float v[4];
    v[0] = fmaf(x0.x, tp0.w, fmaf(x1.x, tp0.z, fmaf(x2.x, tp0.y, fmaf(x3.x, tp0.x, cbv.x))));
    v[1] = fmaf(x0.y, tp1.w, fmaf(x1.y, tp1.z, fmaf(x2.y, tp1.y, fmaf(x3.y, tp1.x, cbv.y))));
    v[2] = fmaf(x0.z, tp2.w, fmaf(x1.z, tp2.z, fmaf(x2.z, tp2.y, fmaf(x3.z, tp2.x, cbv.z))));
    v[3] = fmaf(x0.w, tp3.w, fmaf(x1.w, tp3.z, fmaf(x2.w, tp3.y, fmaf(x3.w, tp3.x, cbv.w))));

    __nv_bfloat16 hh[4], ll[4];
    #pragma unroll
    for (int i = 0; i < 4; i++) {
        float sv = v[i] / (1.f + __expf(-v[i]));
        split_bf16(sv, hh[i], ll[i]);
    }
    size_t o = ((size_t)(b * LL + t)) * DIM + d4;
    *reinterpret_cast<uint2*>(xc_hi + o) = *reinterpret_cast<uint2*>(hh);
    *reinterpret_cast<uint2*>(xc_lo + o) = *reinterpret_cast<uint2*>(ll);
}

// ---------------- chunked selective scan --------------------------------------
// dtv comes pre-softplus'd from the dt GEMM epilogue.
// pass1 runs only chunks 0..NC-2 (last chunk's hend/P are never consumed).
#define CH 32

__global__ __launch_bounds__(128) void scan_pass1(
    const float* __restrict__ xdbl, const float* __restrict__ dtv_buf,
    const __nv_bfloat16* __restrict__ xc_hi, const __nv_bfloat16* __restrict__ xc_lo,
    const float* __restrict__ A_log,
    float* __restrict__ hend, float* __restrict__ Pbuf)
{
    const int b = blockIdx.z, c = blockIdx.y;
    const int d = blockIdx.x * 128 + threadIdx.x;
    float a[DS], h[DS];
    bool pow_ok = true;
    #pragma unroll
    for (int s = 0; s < DS; s++) {
        a[s] = -__expf(A_log[(size_t)d * DS + s]);
        pow_ok = pow_ok && (fabsf(-a[s] - (float)(s + 1)) < 1e-3f);
        h[s] = 0.f;
    }
    float sumdt = 0.f;
    __shared__ float sB[CH][DS];
    const int tbase = c * CS;

    for (int t0 = 0; t0 < CS; t0 += CH) {
        __syncthreads();
        for (int idx = threadIdx.x; idx < CH * DS; idx += 128) {
            int r = idx >> 4, col = idx & 15;
            sB[r][col] = xdbl[(size_t)(b * LL + tbase + t0 + r) * NXD + DTRK + col];
        }
        __syncthreads();
        if (pow_ok) {
            #pragma unroll 4
            for (int r = 0; r < CH; r++) {
                size_t off = (size_t)(b * LL + tbase + t0 + r) * DIM + d;
                float dtv = dtv_buf[off];
                sumdt += dtv;
                float x = __bfloat162float(xc_hi[off]) + __bfloat162float(xc_lo[off]);
                float dtx = dtv * x;
                float pw[DS];
                pow_tree(__expf(-dtv), pw);
                #pragma unroll
                for (int s = 0; s < DS; s++)
                    h[s] = fmaf(pw[s], h[s], dtx * sB[r][s]);
            }
        } else {
            #pragma unroll 4
            for (int r = 0; r < CH; r++) {
                size_t off = (size_t)(b * LL + tbase + t0 + r) * DIM + d;
                float dtv = dtv_buf[off];
                sumdt += dtv;
                float x = __bfloat162float(xc_hi[off]) + __bfloat162float(xc_lo[off]);
                float dtx = dtv * x;
                #pragma unroll
                for (int s = 0; s < DS; s++)
                    h[s] = fmaf(__expf(dtv * a[s]), h[s], dtx * sB[r][s]);
            }
        }
    }
    size_t obase = ((size_t)(b * NC + c) * DS) * DIM + d;
    if (pow_ok) {
        float pw[DS];
        pow_tree(__expf(-sumdt), pw);
        #pragma unroll
        for (int s = 0; s < DS; s++) {
            hend[obase + (size_t)s * DIM] = h[s];
            Pbuf[obase + (size_t)s * DIM] = pw[s];
        }
    } else {
        #pragma unroll
        for (int s = 0; s < DS; s++) {
            hend[obase + (size_t)s * DIM] = h[s];
            Pbuf[obase + (size_t)s * DIM] = __expf(a[s] * sumdt);
        }
    }
}

__global__ __launch_bounds__(128) void scan_pass3(
    const float* __restrict__ xdbl, const float* __restrict__ dtv_buf,
    const __nv_bfloat16* __restrict__ xc_hi, const __nv_bfloat16* __restrict__ xc_lo,
    const float* __restrict__ xz,
    const float* __restrict__ A_log, const float* __restrict__ Dp,
    const float* __restrict__ hend, const float* __restrict__ Pbuf,
    __nv_bfloat16* __restrict__ y_hi, __nv_bfloat16* __restrict__ y_lo)
{
    const int b = blockIdx.z, c = blockIdx.y;
    const int d = blockIdx.x * 128 + threadIdx.x;
    float a[DS], h[DS];
    bool pow_ok = true;
    #pragma unroll
    for (int s = 0; s < DS; s++) {
        a[s] = -__expf(A_log[(size_t)d * DS + s]);
        pow_ok = pow_ok && (fabsf(-a[s] - (float)(s + 1)) < 1e-3f);
        h[s] = 0.f;
    }
    for (int cc = 0; cc < c; cc++) {
        size_t base = ((size_t)(b * NC + cc) * DS) * DIM + d;
        #pragma unroll
        for (int s = 0; s < DS; s++)
            h[s] = fmaf(Pbuf[base + (size_t)s * DIM], h[s],
                        hend[base + (size_t)s * DIM]);
    }
    const float Dd = Dp[d];
    __shared__ float sB[CH][DS];
    __shared__ float sC[CH][DS];
    const int tbase = c * CS;

    for (int t0 = 0; t0 < CS; t0 += CH) {
        __syncthreads();
        for (int idx = threadIdx.x; idx < CH * 32; idx += 128) {
            int r = idx >> 5, col = idx & 31;
            float v = xdbl[(size_t)(b * LL + tbase + t0 + r) * NXD + DTRK + col];
            if (col < DS) sB[r][col] = v; else sC[r][col - DS] = v;
        }
        __syncthreads();
        if (pow_ok) {
            #pragma unroll 4
            for (int r = 0; r < CH; r++) {
                int t = tbase + t0 + r;
                size_t off = (size_t)(b * LL + t) * DIM + d;
                float dtv = dtv_buf[off];
                float x = __bfloat162float(xc_hi[off]) + __bfloat162float(xc_lo[off]);
                float z = xz[(size_t)(b * LL + t) * (2 * DIM) + DIM + d];
                float dtx = dtv * x;
                float y = 0.f;
                float pw[DS];
                pow_tree(__expf(-dtv), pw);
                #pragma unroll
                for (int s = 0; s < DS; s++) {
                    h[s] = fmaf(pw[s], h[s], dtx * sB[r][s]);
                    y = fmaf(h[s], sC[r][s], y);
                }
                float sz = z / (1.f + __expf(-z));
                float yo = (y + Dd * x) * sz;
                __nv_bfloat16 hh, ll; split_bf16(yo, hh, ll);
                y_hi[off] = hh; y_lo[off] = ll;
            }
        } else {
            #pragma unroll 4
            for (int r = 0; r < CH; r++) {
                int t = tbase + t0 + r;
                size_t off = (size_t)(b * LL + t) * DIM + d;
                float dtv = dtv_buf[off];
                float x = __bfloat162float(xc_hi[off]) + __bfloat162float(xc_lo[off]);
                float z = xz[(size_t)(b * LL + t) * (2 * DIM) + DIM + d];
                float dtx = dtv * x;
                float y = 0.f;
                #pragma unroll
                for (int s = 0; s < DS; s++) {
                    h[s] = fmaf(__expf(dtv * a[s]), h[s], dtx * sB[r][s]);
                    y = fmaf(h[s], sC[r][s], y);
                }
                float sz = z / (1.f + __expf(-z));
                float yo = (y + Dd * x) * sz;
                __nv_bfloat16 hh, ll; split_bf16(yo, hh, ll);
                y_hi[off] = hh; y_lo[off] = ll;
            }
        }
    }
}

// ---------------- launch ------------------------------------------------------
extern "C" void kernel_launch(void* const* d_in, const int* in_sizes, int n_in,
                              void* d_out, int out_size)
{
    const float* x          = (const float*)d_in[0];
    const float* residual   = (const float*)d_in[1];
    const float* ln_w       = (const float*)d_in[2];
    const float* ln_b       = (const float*)d_in[3];
    const float* in_proj_w  = (const float*)d_in[4];
    const float* conv_w     = (const float*)d_in[5];
    const float* conv_b     = (const float*)d_in[6];
    const float* x_proj_w   = (const float*)d_in[7];
    const float* dt_proj_w  = (const float*)d_in[8];
    const float* dt_proj_b  = (const float*)d_in[9];
    const float* A_log      = (const float*)d_in[10];
    const float* D_param    = (const float*)d_in[11];
    const float* out_proj_w = (const float*)d_in[12];

    float* out     = (float*)d_out;
    float* res_out = out + (size_t)BL * DD;

    float *xz, *xdbl, *xpart, *dtv, *hend, *Pbuf;
    __nv_bfloat16 *h_hi, *h_lo, *wi_hi, *wi_lo, *xc_hi, *xc_lo, *xp_hi, *xp_lo;
    __nv_bfloat16 *dta_hi, *dta_lo, *dtw_hi, *dtw_lo, *y_hi, *y_lo, *ow_hi, *ow_lo;
    cudaGetSymbolAddress((void**)&xz,    g_xz);
    cudaGetSymbolAddress((void**)&xdbl,  g_xdbl);
    cudaGetSymbolAddress((void**)&xpart, g_xpart);
    cudaGetSymbolAddress((void**)&dtv,   g_dtv);
    cudaGetSymbolAddress((void**)&hend,  g_hend);
    cudaGetSymbolAddress((void**)&Pbuf,  g_P);
    cudaGetSymbolAddress((void**)&h_hi,  g_h_hi);  cudaGetSymbolAddress((void**)&h_lo,  g_h_lo);
    cudaGetSymbolAddress((void**)&wi_hi, g_wi_hi); cudaGetSymbolAddress((void**)&wi_lo, g_wi_lo);
    cudaGetSymbolAddress((void**)&xc_hi, g_xc_hi); cudaGetSymbolAddress((void**)&xc_lo, g_xc_lo);
    cudaGetSymbolAddress((void**)&xp_hi, g_xp_hi); cudaGetSymbolAddress((void**)&xp_lo, g_xp_lo);
    cudaGetSymbolAddress((void**)&dta_hi,g_dta_hi);cudaGetSymbolAddress((void**)&dta_lo,g_dta_lo);
    cudaGetSymbolAddress((void**)&dtw_hi,g_dtw_hi);cudaGetSymbolAddress((void**)&dtw_lo,g_dtw_lo);
    cudaGetSymbolAddress((void**)&y_hi,  g_y_hi);  cudaGetSymbolAddress((void**)&y_lo,  g_y_lo);
    cudaGetSymbolAddress((void**)&ow_hi, g_ow_hi); cudaGetSymbolAddress((void**)&ow_lo, g_ow_lo);

    cudaFuncSetAttribute(tc_gemm, cudaFuncAttributeMaxDynamicSharedMemorySize, GSMEM);

    // 0) in_proj weight cvt
    {
        long t1 = (long)2 * DIM * DD;
        cvt_flat_kernel<<<(int)((t1 + 255) / 256), 256>>>(in_proj_w, t1, wi_hi, wi_lo);
    }
    // 1) remaining weights (fused)
    cvt_rest_kernel<<<(int)((C3 + 255) / 256), 256>>>(
        x_proj_w, dt_proj_w, out_proj_w,
        xp_hi, xp_lo, dtw_hi, dtw_lo, ow_hi, ow_lo);

    // 2) residual = x + residual; h = LN(residual) -> hi/lo
    addnorm_kernel<<<BL, 256>>>(x, residual, ln_w, ln_b, res_out, h_hi, h_lo);

    // 3) xz = h @ in_proj_w^T   (M=4096, N=4096, K=1024)   <-- ncu window
    tc_gemm<<<dim3(2 * DIM / 128, BL / 128), 256, GSMEM>>>(
        h_hi, h_lo, wi_hi, wi_lo, xz, 2 * DIM, 2 * DIM, DD, DD, 0, (const float*)0);

    // 4) xc = silu(causal_conv(x_in)) -> hi/lo, x4 vectorized
    conv_silu_kernel<<<(BB * LL * (DIM / 4) + 255) / 256, 256>>>(
        xz, conv_w, conv_b, xc_hi, xc_lo);

    // 5) x_dbl = xc @ x_proj_w^T (M=4096, N=96, K=2048), 8-way split-K + reduce
    tc_gemm<<<dim3(1, BL / 128, KSPL), 256, GSMEM>>>(
        xc_hi, xc_lo, xp_hi, xp_lo, xpart, NXD, NXD, DIM, DIM / KSPL,
        (long)BL * NXD, (const float*)0);
    xpart_reduce_kernel<<<(BL * NXD + 255) / 256, 256>>>(xpart, xdbl, dta_hi, dta_lo);

    // 6) dtv = softplus(dt_r @ dt_proj_w^T + dt_bias)  (fused epilogue)
    tc_gemm<<<dim3(DIM / 128, BL / 128), 256, GSMEM>>>(
        dta_hi, dta_lo, dtw_hi, dtw_lo, dtv, DIM, DIM, DTRK, DTRK, 0, dt_proj_b);

    // 7) chunked selective scan (pass1 skips the last chunk)
    scan_pass1<<<dim3(DIM / 128, NC - 1, BB), 128>>>(
        xdbl, dtv, xc_hi, xc_lo, A_log, hend, Pbuf);
    scan_pass3<<<dim3(DIM / 128, NC, BB), 128>>>(
        xdbl, dtv, xc_hi, xc_lo, xz, A_log, D_param, hend, Pbuf, y_hi, y_lo);

    // 8) out = y @ out_proj_w^T   (M=4096, N=1024, K=2048)
    tc_gemm<<<dim3(DD / 128, BL / 128), 256, GSMEM>>>(
        y_hi, y_lo, ow_hi, ow_lo, out, DD, DD, DIM, DIM, 0, (const float*)0);
}